// round 6
// baseline (speedup 1.0000x reference)
#include <cuda_runtime.h>
#include <cuda_bf16.h>
#include <math.h>

// ---------------------------------------------------------------------------
// Problem constants
// ---------------------------------------------------------------------------
constexpr int B     = 32;
constexpr int NV    = 1556;          // vertex tokens
constexpr int NI    = 256;           // image tokens
constexpr int NT    = NV + NI;       // 1812 total tokens
constexpr int D     = 512;
constexpr int IMGD  = 2048;

constexpr int M_IMG = B * NI;        // 8192
constexpr int M_Q   = B * NT;        // 57984 (divisible by 128: 453 tiles)
constexpr int M_K   = B * NV;        // 49792 (divisible by 128: 389 tiles)

constexpr float ATTN_SCALE = 0.08838834764831845f;  // (D/4)^-0.5

// ---------------------------------------------------------------------------
// Scratch (device globals; runtime allocation is forbidden)
// ---------------------------------------------------------------------------
__device__ float g_x  [(size_t)B * NT * D];   // concat(verts, img_proj)
__device__ float g_q  [(size_t)B * NT * D];   // normalized q (all tokens)
__device__ float g_k  [(size_t)B * NV * D];   // normalized k (vert tokens only), later g*k
__device__ float g_t  [(size_t)B * NV * D];   // proj output
__device__ float g_logit[(size_t)B * NT];
__device__ float g_stats[2 * B];              // per-batch (max, sumexp)
__device__ float g_gq [(size_t)B * D];        // global query g

// ---------------------------------------------------------------------------
// Generic SGEMM: C[r][0..511] = A'[r][:] @ W^T + bias (+ aux)
//   A row r lives at  A + (r/rpbA)*strideA + (r%rpbA)*K      (K floats per row)
//   C row r lives at  C + (r/rpbO)*strideO + (r%rpbO)*512
//   aux row r (optional) at aux + (r/rpbX)*strideX + (r%rpbX)*512
// W is [512][K] row-major (einsum 'bnd,ed->bne' => C = A @ W^T).
// Tile: BM=128, BN=128, BK=16, 256 threads, 8x8 per thread.
// Inner product uses packed fma.rn.f32x2 (Blackwell FFMA2) for 2x fp32 rate.
// Requires M % 128 == 0 and K % 16 == 0 (true for all five calls).
// ---------------------------------------------------------------------------
#define BM 128
#define BN 128
#define BK 16
#define TM 8
#define TN 8

__global__ __launch_bounds__(256)
void sgemm_kernel(const float* __restrict__ A, int K,
                  int rpbA, long long strideA,
                  const float* __restrict__ W,
                  const float* __restrict__ bias,
                  const float* __restrict__ aux, int rpbX, long long strideX,
                  float* __restrict__ C, int rpbO, long long strideO)
{
    __shared__ __align__(16) float As[2][BK][BM + 4];
    __shared__ __align__(16) float Bs[2][BK][BN + 4];

    const int tid  = threadIdx.x;
    const int bm   = blockIdx.x;
    const int bn   = blockIdx.y;
    const int tRow = tid >> 4;          // 0..15
    const int tCol = tid & 15;          // 0..15

    // global-load indexing: each thread loads 2 float4 per operand per tile
    const int laRow = tid >> 2;         // 0..63
    const int laCol = (tid & 3) * 4;    // 0,4,8,12

    long long aOff[2];
#pragma unroll
    for (int i = 0; i < 2; i++) {
        int r = bm * BM + laRow + i * 64;
        aOff[i] = (long long)(r / rpbA) * strideA + (long long)(r % rpbA) * K;
    }
    const float* Wt = W + (long long)(bn * BN) * K;

    unsigned long long acc[TM][TN / 2];
#pragma unroll
    for (int i = 0; i < TM; i++)
#pragma unroll
        for (int j = 0; j < TN / 2; j++) acc[i][j] = 0ull;

    auto load_tiles = [&](int kt, int nbuf) {
        const int kbase = kt * BK;
#pragma unroll
        for (int i = 0; i < 2; i++) {
            const int mrow = laRow + i * 64;
            float4 va = *(const float4*)(A + aOff[i] + kbase + laCol);
            As[nbuf][laCol + 0][mrow] = va.x;
            As[nbuf][laCol + 1][mrow] = va.y;
            As[nbuf][laCol + 2][mrow] = va.z;
            As[nbuf][laCol + 3][mrow] = va.w;
            float4 vb = *(const float4*)(Wt + (long long)mrow * K + kbase + laCol);
            Bs[nbuf][laCol + 0][mrow] = vb.x;
            Bs[nbuf][laCol + 1][mrow] = vb.y;
            Bs[nbuf][laCol + 2][mrow] = vb.z;
            Bs[nbuf][laCol + 3][mrow] = vb.w;
        }
    };

    load_tiles(0, 0);
    __syncthreads();

    const int nk = K / BK;
    for (int kt = 0; kt < nk; kt++) {
        const int buf = kt & 1;
        if (kt + 1 < nk) load_tiles(kt + 1, buf ^ 1);

#pragma unroll
        for (int kk = 0; kk < BK; kk++) {
            unsigned long long a2[TM];
#pragma unroll
            for (int i = 0; i < TM; i++) {
                float av = As[buf][kk][tRow * TM + i];
                asm("mov.b64 %0, {%1, %1};" : "=l"(a2[i]) : "f"(av));
            }
            unsigned long long b2[TN / 2];
            const unsigned long long* bp =
                (const unsigned long long*)&Bs[buf][kk][tCol * TN];
#pragma unroll
            for (int j = 0; j < TN / 2; j++) b2[j] = bp[j];

#pragma unroll
            for (int i = 0; i < TM; i++)
#pragma unroll
                for (int j = 0; j < TN / 2; j++)
                    asm("fma.rn.f32x2 %0, %1, %2, %3;"
                        : "=l"(acc[i][j])
                        : "l"(a2[i]), "l"(b2[j]), "l"(acc[i][j]));
        }
        __syncthreads();
    }

    // epilogue: unpack, add bias (+aux), store float4
#pragma unroll
    for (int i = 0; i < TM; i++) {
        const int r = bm * BM + tRow * TM + i;
        const long long co = (long long)(r / rpbO) * strideO +
                             (long long)(r % rpbO) * 512;
        long long xo = 0;
        if (aux) xo = (long long)(r / rpbX) * strideX +
                      (long long)(r % rpbX) * 512;
#pragma unroll
        for (int jp = 0; jp < 2; jp++) {
            const int e = bn * BN + tCol * TN + jp * 4;
            float4 v;
            asm("mov.b64 {%0, %1}, %2;" : "=f"(v.x), "=f"(v.y) : "l"(acc[i][jp * 2 + 0]));
            asm("mov.b64 {%0, %1}, %2;" : "=f"(v.z), "=f"(v.w) : "l"(acc[i][jp * 2 + 1]));
            float4 bb = *(const float4*)(bias + e);
            v.x += bb.x; v.y += bb.y; v.z += bb.z; v.w += bb.w;
            if (aux) {
                float4 ax = *(const float4*)(aux + xo + e);
                v.x += ax.x; v.y += ax.y; v.z += ax.z; v.w += ax.w;
            }
            *(float4*)(C + co + e) = v;
        }
    }
}

// ---------------------------------------------------------------------------
// Elementwise / reduction kernels
// ---------------------------------------------------------------------------

// x[:, :NV, :] = verts_f  (strided copy, float4 granularity)
__global__ void copy_verts_kernel(const float4* __restrict__ src, float4* __restrict__ x)
{
    long long idx = (long long)blockIdx.x * blockDim.x + threadIdx.x;
    const long long total = (long long)M_K * (D / 4);
    if (idx >= total) return;
    const int  c = (int)(idx & 127);
    const long long r = idx >> 7;
    const int  b = (int)(r / NV);
    const int  n = (int)(r % NV);
    x[((long long)b * NT + n) * (D / 4) + c] = src[idx];
}

// row-wise L2 normalize (one warp per row); optionally compute logits
__global__ void l2norm_kernel(float* __restrict__ Q, int M,
                              const float* __restrict__ wg,
                              float* __restrict__ logit)
{
    const int gw   = (int)(((long long)blockIdx.x * blockDim.x + threadIdx.x) >> 5);
    const int lane = threadIdx.x & 31;
    if (gw >= M) return;
    float4* row = (float4*)(Q + (long long)gw * D);
    float4 v[4];
    float ss = 0.f, dg = 0.f;
#pragma unroll
    for (int i = 0; i < 4; i++) {
        v[i] = row[lane + 32 * i];
        ss += v[i].x * v[i].x + v[i].y * v[i].y + v[i].z * v[i].z + v[i].w * v[i].w;
    }
    if (wg) {
#pragma unroll
        for (int i = 0; i < 4; i++) {
            float4 w = ((const float4*)wg)[lane + 32 * i];
            dg += v[i].x * w.x + v[i].y * w.y + v[i].z * w.z + v[i].w * w.w;
        }
    }
#pragma unroll
    for (int o = 16; o > 0; o >>= 1) {
        ss += __shfl_xor_sync(0xffffffffu, ss, o);
        dg += __shfl_xor_sync(0xffffffffu, dg, o);
    }
    const float inv = 1.f / fmaxf(sqrtf(ss), 1e-12f);
#pragma unroll
    for (int i = 0; i < 4; i++) {
        v[i].x *= inv; v[i].y *= inv; v[i].z *= inv; v[i].w *= inv;
        row[lane + 32 * i] = v[i];
    }
    if (wg && lane == 0) logit[gw] = dg * inv * ATTN_SCALE;
}

// per-batch softmax statistics over NT tokens
__global__ void softmax_stats_kernel(const float* __restrict__ logit,
                                     float* __restrict__ stats)
{
    const int b = blockIdx.x;
    const int tid = threadIdx.x;
    __shared__ float red[256];
    float mx = -1e30f;
    for (int n = tid; n < NT; n += 256) mx = fmaxf(mx, logit[b * NT + n]);
    red[tid] = mx; __syncthreads();
    for (int s = 128; s > 0; s >>= 1) {
        if (tid < s) red[tid] = fmaxf(red[tid], red[tid + s]);
        __syncthreads();
    }
    const float m = red[0]; __syncthreads();
    float se = 0.f;
    for (int n = tid; n < NT; n += 256) se += expf(logit[b * NT + n] - m);
    red[tid] = se; __syncthreads();
    for (int s = 128; s > 0; s >>= 1) {
        if (tid < s) red[tid] += red[tid + s];
        __syncthreads();
    }
    if (tid == 0) { stats[2 * b] = m; stats[2 * b + 1] = red[0]; }
}

// g[b,d] = sum_n softmax(a)[b,n] * q[b,n,d]
__global__ void compute_g_kernel(const float* __restrict__ q,
                                 const float* __restrict__ logit,
                                 const float* __restrict__ stats,
                                 float* __restrict__ g)
{
    const int b = blockIdx.x;
    const int d = blockIdx.y * 128 + threadIdx.x;
    const float m = stats[2 * b];
    const float inv_s = 1.f / stats[2 * b + 1];
    __shared__ float w[128];
    float acc = 0.f;
    const float* qb = q + (long long)b * NT * D;
    for (int n0 = 0; n0 < NT; n0 += 128) {
        const int n = n0 + threadIdx.x;
        w[threadIdx.x] = (n < NT) ? expf(logit[b * NT + n] - m) * inv_s : 0.f;
        __syncthreads();
        const int lim = min(128, NT - n0);
        for (int j = 0; j < lim; j++)
            acc += w[j] * qb[(long long)(n0 + j) * D + d];
        __syncthreads();
    }
    g[b * D + d] = acc;
}

// k[b,n,:] *= g[b,:]
__global__ void scale_k_kernel(float4* __restrict__ k, const float4* __restrict__ g)
{
    long long idx = (long long)blockIdx.x * blockDim.x + threadIdx.x;
    const long long total = (long long)M_K * (D / 4);
    if (idx >= total) return;
    const int  c = (int)(idx & 127);
    const long long r = idx >> 7;
    const int  b = (int)(r / NV);
    float4 kv = k[idx];
    const float4 gv = g[b * (D / 4) + c];
    kv.x *= gv.x; kv.y *= gv.y; kv.z *= gv.z; kv.w *= gv.w;
    k[idx] = kv;
}

// ---------------------------------------------------------------------------
// launch
// ---------------------------------------------------------------------------
extern "C" void kernel_launch(void* const* d_in, const int* in_sizes, int n_in,
                              void* d_out, int out_size)
{
    (void)in_sizes; (void)n_in; (void)out_size;

    const float* verts_f = (const float*)d_in[0];
    const float* img_f   = (const float*)d_in[1];
    const float* fc_w    = (const float*)d_in[2];
    const float* fc_b    = (const float*)d_in[3];
    const float* q_w     = (const float*)d_in[4];
    const float* q_b     = (const float*)d_in[5];
    const float* k_w     = (const float*)d_in[6];
    const float* k_b     = (const float*)d_in[7];
    const float* w_g     = (const float*)d_in[8];
    const float* proj_w  = (const float*)d_in[9];
    const float* proj_b  = (const float*)d_in[10];
    const float* final_w = (const float*)d_in[11];
    const float* final_b = (const float*)d_in[12];
    float* out = (float*)d_out;

    float *x, *q, *k, *t, *logit, *stats, *gq;
    cudaGetSymbolAddress((void**)&x,     g_x);
    cudaGetSymbolAddress((void**)&q,     g_q);
    cudaGetSymbolAddress((void**)&k,     g_k);
    cudaGetSymbolAddress((void**)&t,     g_t);
    cudaGetSymbolAddress((void**)&logit, g_logit);
    cudaGetSymbolAddress((void**)&stats, g_stats);
    cudaGetSymbolAddress((void**)&gq,    g_gq);

    const long long sNT = (long long)NT * D;      // x/q per-batch stride
    const long long ew_total = (long long)M_K * (D / 4);
    const int ew_blocks = (int)((ew_total + 255) / 256);

    // 1) x[:, :NV] = verts_f
    copy_verts_kernel<<<ew_blocks, 256>>>((const float4*)verts_f, (float4*)x);

    // 2) x[:, NV:] = img_f @ fc_w^T + fc_b
    sgemm_kernel<<<dim3(M_IMG / BM, 4), 256>>>(
        img_f, IMGD, M_IMG, 0LL, fc_w, fc_b,
        nullptr, 1, 0LL,
        x + (long long)NV * D, NI, sNT);

    // 3) q = x @ q_w^T + q_b  (all tokens), then l2norm + logits
    sgemm_kernel<<<dim3(M_Q / BM, 4), 256>>>(
        x, D, M_Q, 0LL, q_w, q_b,
        nullptr, 1, 0LL,
        q, M_Q, 0LL);
    l2norm_kernel<<<(M_Q * 32 + 255) / 256, 256>>>(q, M_Q, w_g, logit);

    // 4) k = x_vert @ k_w^T + k_b  (vertex tokens only), then l2norm
    sgemm_kernel<<<dim3(M_K / BM, 4), 256>>>(
        x, D, NV, sNT, k_w, k_b,
        nullptr, 1, 0LL,
        k, M_K, 0LL);
    l2norm_kernel<<<(M_K * 32 + 255) / 256, 256>>>(k, M_K, nullptr, nullptr);

    // 5) softmax over tokens; global query g
    softmax_stats_kernel<<<B, 256>>>(logit, stats);
    compute_g_kernel<<<dim3(B, 4), 128>>>(q, logit, stats, gq);

    // 6) k <- g * k
    scale_k_kernel<<<ew_blocks, 256>>>((float4*)k, (const float4*)gq);

    // 7) t = (g*k) @ proj_w^T + proj_b + q_vert
    sgemm_kernel<<<dim3(M_K / BM, 4), 256>>>(
        k, D, M_K, 0LL, proj_w, proj_b,
        q, NV, sNT,
        t, M_K, 0LL);

    // 8) out = t @ final_w^T + final_b + verts_f
    sgemm_kernel<<<dim3(M_K / BM, 4), 256>>>(
        t, D, M_K, 0LL, final_w, final_b,
        verts_f, M_K, 0LL,
        out, M_K, 0LL);
}

// round 8
// speedup vs baseline: 2.2427x; 2.2427x over previous
#include <cuda_runtime.h>
#include <cuda_bf16.h>
#include <stdint.h>
#include <math.h>

// ---------------------------------------------------------------------------
// Problem constants
// ---------------------------------------------------------------------------
constexpr int B     = 32;
constexpr int NV    = 1556;
constexpr int NI    = 256;
constexpr int NT    = NV + NI;       // 1812
constexpr int D     = 512;
constexpr int IMGD  = 2048;

constexpr int M_IMG = B * NI;        // 8192  = 64*128
constexpr int M_Q   = B * NT;        // 57984 = 453*128
constexpr int M_K   = B * NV;        // 49792 = 389*128

constexpr float ATTN_SCALE = 0.08838834764831845f;  // (D/4)^-0.5

// weight split offsets (elements) in the packed weight buffers
constexpr long long OFF_FC = 0;
constexpr long long OFF_QW = (long long)D * IMGD;
constexpr long long OFF_KW = OFF_QW + (long long)D * D;
constexpr long long OFF_PW = OFF_KW + (long long)D * D;
constexpr long long OFF_FW = OFF_PW + (long long)D * D;
constexpr long long W_TOTAL = OFF_FW + (long long)D * D;

// ---------------------------------------------------------------------------
// Scratch (device globals; runtime allocation is forbidden)
// ---------------------------------------------------------------------------
__device__ __nv_bfloat16 g_xhi[(size_t)M_Q * D];
__device__ __nv_bfloat16 g_xlo[(size_t)M_Q * D];
__device__ __nv_bfloat16 g_ihi[(size_t)M_IMG * IMGD];
__device__ __nv_bfloat16 g_ilo[(size_t)M_IMG * IMGD];
__device__ float         g_q  [(size_t)M_Q * D];
__device__ float         g_k  [(size_t)M_K * D];
__device__ __nv_bfloat16 g_gkhi[(size_t)M_K * D];
__device__ __nv_bfloat16 g_gklo[(size_t)M_K * D];
__device__ __nv_bfloat16 g_thi[(size_t)M_K * D];
__device__ __nv_bfloat16 g_tlo[(size_t)M_K * D];
__device__ __nv_bfloat16 g_whi[(size_t)W_TOTAL];
__device__ __nv_bfloat16 g_wlo[(size_t)W_TOTAL];
__device__ float g_logit[(size_t)B * NT];
__device__ float g_stats[2 * B];
__device__ float g_gq   [(size_t)B * D];

// ---------------------------------------------------------------------------
// PTX helpers (ALL baseline sm_80-class: valid under compute_103 / sm_103)
// ---------------------------------------------------------------------------
__device__ __forceinline__ uint32_t smem_u32(const void* p) {
    uint32_t a;
    asm("{ .reg .u64 t; cvta.to.shared.u64 t, %1; cvt.u32.u64 %0, t; }"
        : "=r"(a) : "l"(p));
    return a;
}

#define CP_ASYNC16(dst, src) \
    asm volatile("cp.async.cg.shared.global [%0], [%1], 16;" \
                 :: "r"(dst), "l"(src) : "memory")
#define CP_COMMIT() asm volatile("cp.async.commit_group;" ::: "memory")
#define CP_WAIT(n)  asm volatile("cp.async.wait_group %0;" :: "n"(n) : "memory")

#define LDSM4(r0, r1, r2, r3, addr) \
    asm volatile("ldmatrix.sync.aligned.m8n8.x4.shared.b16 {%0,%1,%2,%3}, [%4];" \
                 : "=r"(r0), "=r"(r1), "=r"(r2), "=r"(r3) : "r"(addr))

#define MMA16816(c, a, b0, b1) \
    asm volatile("mma.sync.aligned.m16n8k16.row.col.f32.bf16.bf16.f32 " \
                 "{%0,%1,%2,%3},{%4,%5,%6,%7},{%8,%9},{%0,%1,%2,%3};" \
                 : "+f"((c)[0]), "+f"((c)[1]), "+f"((c)[2]), "+f"((c)[3]) \
                 : "r"((a)[0]), "r"((a)[1]), "r"((a)[2]), "r"((a)[3]), \
                   "r"(b0), "r"(b1))

// ---------------------------------------------------------------------------
// bf16 split helpers
// ---------------------------------------------------------------------------
__device__ __forceinline__ uint32_t pk(__nv_bfloat16 a, __nv_bfloat16 b) {
    __nv_bfloat162 t; t.x = a; t.y = b;
    return *reinterpret_cast<uint32_t*>(&t);
}
__device__ __forceinline__ void split2(float x, float y, uint32_t& h, uint32_t& l) {
    __nv_bfloat16 hx = __float2bfloat16(x), hy = __float2bfloat16(y);
    __nv_bfloat16 lx = __float2bfloat16(x - __bfloat162float(hx));
    __nv_bfloat16 ly = __float2bfloat16(y - __bfloat162float(hy));
    h = pk(hx, hy); l = pk(lx, ly);
}
__device__ __forceinline__ void split4(const float4 v, uint2& h, uint2& l) {
    split2(v.x, v.y, h.x, l.x);
    split2(v.z, v.w, h.y, l.y);
}

// ---------------------------------------------------------------------------
// Tensor-core GEMM (mma.sync bf16, 3-term fp32-split):
//   C[r][0..511] = A[r][:] @ W^T  (+bias, +aux)
// A hi/lo with row remap: row R -> (R/rpbA)*strideA + (R%rpbA)*K (elements)
// W is [512][K] bf16 hi/lo row-major. grid = (M/128, 4), 256 threads.
// Output fp32 (outF) or re-split bf16 (outHi/outLo), row remap rpbO/strideO.
// ---------------------------------------------------------------------------
constexpr int ROWB    = 80;                 // padded row stride (32 bf16 + 16B pad)
constexpr int TILEB   = 128 * ROWB;         // 10240 B per operand tile
constexpr int STAGEB  = 4 * TILEB;          // Ahi,Alo,Bhi,Blo
constexpr int NSTAGE  = 3;
constexpr int SMEM_GEMM = NSTAGE * STAGEB;  // 122880 B

__global__ __launch_bounds__(256, 1)
void mma_gemm(const __nv_bfloat16* __restrict__ Ahi,
              const __nv_bfloat16* __restrict__ Alo,
              int K, int rpbA, long long strideA,
              const __nv_bfloat16* __restrict__ Whi,
              const __nv_bfloat16* __restrict__ Wlo,
              const float* __restrict__ bias,
              const float* __restrict__ aux, int rpbX, long long strideX,
              float* __restrict__ outF,
              __nv_bfloat16* __restrict__ outHi, __nv_bfloat16* __restrict__ outLo,
              int rpbO, long long strideO)
{
    extern __shared__ char smem[];
    const uint32_t sbase = smem_u32(smem);

    const int tid  = threadIdx.x;
    const int wid  = tid >> 5;
    const int lane = tid & 31;
    const int bm   = blockIdx.x, bn = blockIdx.y;
    const int wm   = wid >> 2;          // 0..1  (m 64-row half)
    const int wn   = wid & 3;           // 0..3  (n 32-col quarter)

    // ---- global-load indexing: thread t -> tile row t/2, 16B units (t&1)*2,+1
    const int lr = tid >> 1;            // 0..127
    const int lu = (tid & 1) * 2;       // 0 or 2
    const int aRow = bm * 128 + lr;
    const char* aHiP = (const char*)(Ahi + (long long)(aRow / rpbA) * strideA +
                                           (long long)(aRow % rpbA) * K);
    const char* aLoP = (const char*)(Alo + (long long)(aRow / rpbA) * strideA +
                                           (long long)(aRow % rpbA) * K);
    const char* bHiP = (const char*)(Whi + (long long)(bn * 128 + lr) * K);
    const char* bLoP = (const char*)(Wlo + (long long)(bn * 128 + lr) * K);
    const uint32_t dRow = sbase + (uint32_t)lr * ROWB + (uint32_t)lu * 16;

    auto stage_load = [&](int c, int stg) {
        const uint32_t sd = dRow + (uint32_t)stg * STAGEB;
        const long long go = (long long)c * 64 + lu * 16;
        CP_ASYNC16(sd + 0 * TILEB +  0, aHiP + go);
        CP_ASYNC16(sd + 0 * TILEB + 16, aHiP + go + 16);
        CP_ASYNC16(sd + 1 * TILEB +  0, aLoP + go);
        CP_ASYNC16(sd + 1 * TILEB + 16, aLoP + go + 16);
        CP_ASYNC16(sd + 2 * TILEB +  0, bHiP + go);
        CP_ASYNC16(sd + 2 * TILEB + 16, bHiP + go + 16);
        CP_ASYNC16(sd + 3 * TILEB +  0, bLoP + go);
        CP_ASYNC16(sd + 3 * TILEB + 16, bLoP + go + 16);
    };

    // ---- ldmatrix address components (per warp/lane) ----
    const uint32_t aOffBase = (uint32_t)(wm * 64 + (lane & 15)) * ROWB +
                              (uint32_t)(lane >> 4) * 16;
    const int brow0   = wn * 32 + (lane & 7) + ((lane >> 4) << 3);
    const uint32_t bColOff = (uint32_t)((lane >> 3) & 1) * 16;

    float acc[4][4][4];
#pragma unroll
    for (int i = 0; i < 4; i++)
#pragma unroll
        for (int j = 0; j < 4; j++)
#pragma unroll
            for (int r = 0; r < 4; r++) acc[i][j][r] = 0.f;

    const int nk = K / 32;

    // prologue: stages 0..NSTAGE-2
#pragma unroll
    for (int s = 0; s < NSTAGE - 1; s++) {
        if (s < nk) stage_load(s, s);
        CP_COMMIT();
    }

    for (int c = 0; c < nk; c++) {
        CP_WAIT(NSTAGE - 2);
        __syncthreads();
        if (c + NSTAGE - 1 < nk) stage_load(c + NSTAGE - 1, (c + NSTAGE - 1) % NSTAGE);
        CP_COMMIT();

        const uint32_t sb = sbase + (uint32_t)(c % NSTAGE) * STAGEB;
#pragma unroll
        for (int s = 0; s < 2; s++) {               // two k16 steps per chunk
            uint32_t aH[4][4], aL[4][4];
#pragma unroll
            for (int i = 0; i < 4; i++) {
                const uint32_t aa = sb + aOffBase + (uint32_t)i * (16 * ROWB) + s * 32;
                LDSM4(aH[i][0], aH[i][1], aH[i][2], aH[i][3], aa);
                LDSM4(aL[i][0], aL[i][1], aL[i][2], aL[i][3], aa + TILEB);
            }
            uint32_t bH[4][2], bL[4][2];
#pragma unroll
            for (int jp = 0; jp < 2; jp++) {
                const uint32_t ba = sb + 2 * TILEB +
                                    (uint32_t)(brow0 + jp * 16) * ROWB +
                                    bColOff + s * 32;
                LDSM4(bH[2 * jp][0], bH[2 * jp][1], bH[2 * jp + 1][0], bH[2 * jp + 1][1], ba);
                LDSM4(bL[2 * jp][0], bL[2 * jp][1], bL[2 * jp + 1][0], bL[2 * jp + 1][1], ba + TILEB);
            }
#pragma unroll
            for (int i = 0; i < 4; i++)
#pragma unroll
                for (int j = 0; j < 4; j++) {
                    MMA16816(acc[i][j], aH[i], bH[j][0], bH[j][1]);
                    MMA16816(acc[i][j], aH[i], bL[j][0], bL[j][1]);
                    MMA16816(acc[i][j], aL[i], bH[j][0], bH[j][1]);
                }
        }
        __syncthreads();
    }

    // ---- epilogue ----
    const int l4 = lane >> 2;
    const int l2 = (lane & 3) * 2;
#pragma unroll
    for (int i = 0; i < 4; i++) {
#pragma unroll
        for (int h = 0; h < 2; h++) {
            const int R = bm * 128 + wm * 64 + i * 16 + l4 + h * 8;
            const long long oBase = (long long)(R / rpbO) * strideO +
                                    (long long)(R % rpbO) * 512;
            long long xBase = 0;
            if (aux) xBase = (long long)(R / rpbX) * strideX +
                             (long long)(R % rpbX) * 512;
#pragma unroll
            for (int j = 0; j < 4; j++) {
                const int cb = bn * 128 + wn * 32 + j * 8 + l2;
                float vx = acc[i][j][h * 2 + 0];
                float vy = acc[i][j][h * 2 + 1];
                const float2 bb = *(const float2*)(bias + cb);
                vx += bb.x; vy += bb.y;
                if (aux) {
                    const float2 ax = *(const float2*)(aux + xBase + cb);
                    vx += ax.x; vy += ax.y;
                }
                if (outF) {
                    float2 o; o.x = vx; o.y = vy;
                    *(float2*)(outF + oBase + cb) = o;
                } else {
                    uint32_t hh, ll;
                    split2(vx, vy, hh, ll);
                    *(uint32_t*)(outHi + oBase + cb) = hh;
                    *(uint32_t*)(outLo + oBase + cb) = ll;
                }
            }
        }
    }
}

// ---------------------------------------------------------------------------
// Elementwise / split / reduction kernels (unchanged from passing R5 logic)
// ---------------------------------------------------------------------------
__global__ void split_kernel(const float4* __restrict__ src,
                             uint2* __restrict__ hi, uint2* __restrict__ lo,
                             long long n4)
{
    long long i = (long long)blockIdx.x * blockDim.x + threadIdx.x;
    if (i >= n4) return;
    uint2 h, l;
    split4(src[i], h, l);
    hi[i] = h; lo[i] = l;
}

__global__ void split_verts_kernel(const float4* __restrict__ src,
                                   uint2* __restrict__ xhi, uint2* __restrict__ xlo)
{
    long long idx = (long long)blockIdx.x * blockDim.x + threadIdx.x;
    const long long total = (long long)M_K * (D / 4);
    if (idx >= total) return;
    const int c = (int)(idx & 127);
    const long long r = idx >> 7;
    const int b = (int)(r / NV), n = (int)(r % NV);
    const long long dst = ((long long)b * NT + n) * 128 + c;
    uint2 h, l;
    split4(src[idx], h, l);
    xhi[dst] = h; xlo[dst] = l;
}

__global__ void l2norm_kernel(float* __restrict__ Q, int M,
                              const float* __restrict__ wg,
                              float* __restrict__ logit)
{
    const int gw   = (int)(((long long)blockIdx.x * blockDim.x + threadIdx.x) >> 5);
    const int lane = threadIdx.x & 31;
    if (gw >= M) return;
    float4* row = (float4*)(Q + (long long)gw * D);
    float4 v[4];
    float ss = 0.f, dg = 0.f;
#pragma unroll
    for (int i = 0; i < 4; i++) {
        v[i] = row[lane + 32 * i];
        ss += v[i].x * v[i].x + v[i].y * v[i].y + v[i].z * v[i].z + v[i].w * v[i].w;
    }
    if (wg) {
#pragma unroll
        for (int i = 0; i < 4; i++) {
            float4 w = ((const float4*)wg)[lane + 32 * i];
            dg += v[i].x * w.x + v[i].y * w.y + v[i].z * w.z + v[i].w * w.w;
        }
    }
#pragma unroll
    for (int o = 16; o > 0; o >>= 1) {
        ss += __shfl_xor_sync(0xffffffffu, ss, o);
        dg += __shfl_xor_sync(0xffffffffu, dg, o);
    }
    const float inv = 1.f / fmaxf(sqrtf(ss), 1e-12f);
#pragma unroll
    for (int i = 0; i < 4; i++) {
        v[i].x *= inv; v[i].y *= inv; v[i].z *= inv; v[i].w *= inv;
        row[lane + 32 * i] = v[i];
    }
    if (wg && lane == 0) logit[gw] = dg * inv * ATTN_SCALE;
}

__global__ void softmax_stats_kernel(const float* __restrict__ logit,
                                     float* __restrict__ stats)
{
    const int b = blockIdx.x;
    const int tid = threadIdx.x;
    __shared__ float red[256];
    float mx = -1e30f;
    for (int n = tid; n < NT; n += 256) mx = fmaxf(mx, logit[b * NT + n]);
    red[tid] = mx; __syncthreads();
    for (int s = 128; s > 0; s >>= 1) {
        if (tid < s) red[tid] = fmaxf(red[tid], red[tid + s]);
        __syncthreads();
    }
    const float m = red[0]; __syncthreads();
    float se = 0.f;
    for (int n = tid; n < NT; n += 256) se += expf(logit[b * NT + n] - m);
    red[tid] = se; __syncthreads();
    for (int s = 128; s > 0; s >>= 1) {
        if (tid < s) red[tid] += red[tid + s];
        __syncthreads();
    }
    if (tid == 0) { stats[2 * b] = m; stats[2 * b + 1] = red[0]; }
}

__global__ void compute_g_kernel(const float* __restrict__ q,
                                 const float* __restrict__ logit,
                                 const float* __restrict__ stats,
                                 float* __restrict__ g)
{
    const int b = blockIdx.x;
    const int d = blockIdx.y * 128 + threadIdx.x;
    const float m = stats[2 * b];
    const float inv_s = 1.f / stats[2 * b + 1];
    __shared__ float w[128];
    float acc = 0.f;
    const float* qb = q + (long long)b * NT * D;
    for (int n0 = 0; n0 < NT; n0 += 128) {
        const int n = n0 + threadIdx.x;
        w[threadIdx.x] = (n < NT) ? expf(logit[b * NT + n] - m) * inv_s : 0.f;
        __syncthreads();
        const int lim = min(128, NT - n0);
        for (int j = 0; j < lim; j++)
            acc += w[j] * qb[(long long)(n0 + j) * D + d];
        __syncthreads();
    }
    g[b * D + d] = acc;
}

__global__ void scale_split_k_kernel(const float4* __restrict__ k,
                                     const float4* __restrict__ g,
                                     uint2* __restrict__ hi, uint2* __restrict__ lo)
{
    long long idx = (long long)blockIdx.x * blockDim.x + threadIdx.x;
    const long long total = (long long)M_K * (D / 4);
    if (idx >= total) return;
    const int c = (int)(idx & 127);
    const int b = (int)((idx >> 7) / NV);
    float4 kv = k[idx];
    const float4 gv = g[b * 128 + c];
    kv.x *= gv.x; kv.y *= gv.y; kv.z *= gv.z; kv.w *= gv.w;
    uint2 h, l;
    split4(kv, h, l);
    hi[idx] = h; lo[idx] = l;
}

// ---------------------------------------------------------------------------
// launch
// ---------------------------------------------------------------------------
extern "C" void kernel_launch(void* const* d_in, const int* in_sizes, int n_in,
                              void* d_out, int out_size)
{
    (void)in_sizes; (void)n_in; (void)out_size;

    const float* verts_f = (const float*)d_in[0];
    const float* img_f   = (const float*)d_in[1];
    const float* fc_w    = (const float*)d_in[2];
    const float* fc_b    = (const float*)d_in[3];
    const float* q_w     = (const float*)d_in[4];
    const float* q_b     = (const float*)d_in[5];
    const float* k_w     = (const float*)d_in[6];
    const float* k_b     = (const float*)d_in[7];
    const float* w_g     = (const float*)d_in[8];
    const float* proj_w  = (const float*)d_in[9];
    const float* proj_b  = (const float*)d_in[10];
    const float* final_w = (const float*)d_in[11];
    const float* final_b = (const float*)d_in[12];
    float* out = (float*)d_out;

    __nv_bfloat16 *xhi, *xlo, *ihi, *ilo, *gkhi, *gklo, *thi, *tlo, *whi, *wlo;
    float *q, *k, *logit, *stats, *gq;
    cudaGetSymbolAddress((void**)&xhi,  g_xhi);
    cudaGetSymbolAddress((void**)&xlo,  g_xlo);
    cudaGetSymbolAddress((void**)&ihi,  g_ihi);
    cudaGetSymbolAddress((void**)&ilo,  g_ilo);
    cudaGetSymbolAddress((void**)&gkhi, g_gkhi);
    cudaGetSymbolAddress((void**)&gklo, g_gklo);
    cudaGetSymbolAddress((void**)&thi,  g_thi);
    cudaGetSymbolAddress((void**)&tlo,  g_tlo);
    cudaGetSymbolAddress((void**)&whi,  g_whi);
    cudaGetSymbolAddress((void**)&wlo,  g_wlo);
    cudaGetSymbolAddress((void**)&q,     g_q);
    cudaGetSymbolAddress((void**)&k,     g_k);
    cudaGetSymbolAddress((void**)&logit, g_logit);
    cudaGetSymbolAddress((void**)&stats, g_stats);
    cudaGetSymbolAddress((void**)&gq,    g_gq);

    cudaFuncSetAttribute(mma_gemm, cudaFuncAttributeMaxDynamicSharedMemorySize,
                         SMEM_GEMM);

    const long long sNT = (long long)NT * D;
    const long long ewT = (long long)M_K * (D / 4);
    const int ewB = (int)((ewT + 255) / 256);

    // --- input splits ---
    auto splt = [&](const float* src, __nv_bfloat16* h, __nv_bfloat16* l, long long n) {
        long long n4 = n / 4;
        split_kernel<<<(int)((n4 + 255) / 256), 256>>>(
            (const float4*)src, (uint2*)h, (uint2*)l, n4);
    };
    splt(fc_w,    whi + OFF_FC, wlo + OFF_FC, (long long)D * IMGD);
    splt(q_w,     whi + OFF_QW, wlo + OFF_QW, (long long)D * D);
    splt(k_w,     whi + OFF_KW, wlo + OFF_KW, (long long)D * D);
    splt(proj_w,  whi + OFF_PW, wlo + OFF_PW, (long long)D * D);
    splt(img_f,   ihi, ilo, (long long)M_IMG * IMGD);
    splt(final_w, whi + OFF_FW, wlo + OFF_FW, (long long)D * D);
    split_verts_kernel<<<ewB, 256>>>((const float4*)verts_f,
                                     (uint2*)xhi, (uint2*)xlo);

    // --- 1) x[:, NV:] = img_f @ fc_w^T + fc_b  (split output into x hi/lo) ---
    mma_gemm<<<dim3(M_IMG / 128, 4), 256, SMEM_GEMM>>>(
        ihi, ilo, IMGD, M_IMG, 0LL,
        whi + OFF_FC, wlo + OFF_FC, fc_b,
        nullptr, 1, 0LL,
        nullptr, xhi + (long long)NV * D, xlo + (long long)NV * D,
        NI, sNT);

    // --- 2) q = x @ q_w^T + q_b (all tokens, fp32 out) ---
    mma_gemm<<<dim3(M_Q / 128, 4), 256, SMEM_GEMM>>>(
        xhi, xlo, D, M_Q, 0LL,
        whi + OFF_QW, wlo + OFF_QW, q_b,
        nullptr, 1, 0LL,
        q, nullptr, nullptr, M_Q, 0LL);
    l2norm_kernel<<<(M_Q * 32 + 255) / 256, 256>>>(q, M_Q, w_g, logit);

    // --- 3) k = x_vert @ k_w^T + k_b (vertex tokens, fp32 out) ---
    mma_gemm<<<dim3(M_K / 128, 4), 256, SMEM_GEMM>>>(
        xhi, xlo, D, NV, sNT,
        whi + OFF_KW, wlo + OFF_KW, k_b,
        nullptr, 1, 0LL,
        k, nullptr, nullptr, M_K, 0LL);
    l2norm_kernel<<<(M_K * 32 + 255) / 256, 256>>>(k, M_K, nullptr, nullptr);

    // --- 4) softmax + global query ---
    softmax_stats_kernel<<<B, 256>>>(logit, stats);
    compute_g_kernel<<<dim3(B, 4), 128>>>(q, logit, stats, gq);

    // --- 5) gk = g * k, split ---
    scale_split_k_kernel<<<ewB, 256>>>((const float4*)k, (const float4*)gq,
                                       (uint2*)gkhi, (uint2*)gklo);

    // --- 6) t = gk @ proj_w^T + proj_b + q_vert (split output) ---
    mma_gemm<<<dim3(M_K / 128, 4), 256, SMEM_GEMM>>>(
        gkhi, gklo, D, M_K, 0LL,
        whi + OFF_PW, wlo + OFF_PW, proj_b,
        q, NV, sNT,
        nullptr, thi, tlo, M_K, 0LL);

    // --- 7) out = t @ final_w^T + final_b + verts_f (fp32 out) ---
    mma_gemm<<<dim3(M_K / 128, 4), 256, SMEM_GEMM>>>(
        thi, tlo, D, M_K, 0LL,
        whi + OFF_FW, wlo + OFF_FW, final_b,
        verts_f, M_K, 0LL,
        out, nullptr, nullptr, M_K, 0LL);
}

// round 10
// speedup vs baseline: 2.5488x; 1.1365x over previous
#include <cuda_runtime.h>
#include <cuda_bf16.h>
#include <stdint.h>
#include <math.h>

// ---------------------------------------------------------------------------
// Problem constants
// ---------------------------------------------------------------------------
constexpr int B     = 32;
constexpr int NV    = 1556;
constexpr int NI    = 256;
constexpr int NT    = NV + NI;       // 1812
constexpr int D     = 512;
constexpr int IMGD  = 2048;

constexpr int M_IMG = B * NI;        // 8192  = 64*128
constexpr int M_Q   = B * NT;        // 57984 = 453*128
constexpr int M_K   = B * NV;        // 49792 = 389*128

constexpr float ATTN_SCALE = 0.08838834764831845f;  // (D/4)^-0.5

// weight split offsets (elements) in the packed weight buffers
constexpr long long OFF_FC = 0;
constexpr long long OFF_QW = (long long)D * IMGD;
constexpr long long OFF_KW = OFF_QW + (long long)D * D;
constexpr long long OFF_PW = OFF_KW + (long long)D * D;
constexpr long long OFF_FW = OFF_PW + (long long)D * D;
constexpr long long W_TOTAL = OFF_FW + (long long)D * D;

// ---------------------------------------------------------------------------
// Scratch (device globals; runtime allocation is forbidden)
// ---------------------------------------------------------------------------
__device__ __nv_bfloat16 g_xhi[(size_t)M_Q * D];
__device__ __nv_bfloat16 g_xlo[(size_t)M_Q * D];
__device__ __nv_bfloat16 g_ihi[(size_t)M_IMG * IMGD];
__device__ __nv_bfloat16 g_ilo[(size_t)M_IMG * IMGD];
__device__ float         g_q  [(size_t)M_Q * D];
__device__ float         g_k  [(size_t)M_K * D];
__device__ __nv_bfloat16 g_gkhi[(size_t)M_K * D];
__device__ __nv_bfloat16 g_gklo[(size_t)M_K * D];
__device__ __nv_bfloat16 g_thi[(size_t)M_K * D];
__device__ __nv_bfloat16 g_tlo[(size_t)M_K * D];
__device__ __nv_bfloat16 g_whi[(size_t)W_TOTAL];
__device__ __nv_bfloat16 g_wlo[(size_t)W_TOTAL];
__device__ float g_logit[(size_t)B * NT];
__device__ float g_stats[2 * B];
__device__ float g_gq   [(size_t)B * D];

// ---------------------------------------------------------------------------
// PTX helpers (ALL baseline sm_80-class: valid under compute_103 / sm_103)
// ---------------------------------------------------------------------------
__device__ __forceinline__ uint32_t smem_u32(const void* p) {
    uint32_t a;
    asm("{ .reg .u64 t; cvta.to.shared.u64 t, %1; cvt.u32.u64 %0, t; }"
        : "=r"(a) : "l"(p));
    return a;
}

#define CP_ASYNC16(dst, src) \
    asm volatile("cp.async.cg.shared.global [%0], [%1], 16;" \
                 :: "r"(dst), "l"(src) : "memory")
#define CP_COMMIT() asm volatile("cp.async.commit_group;" ::: "memory")
#define CP_WAIT(n)  asm volatile("cp.async.wait_group %0;" :: "n"(n) : "memory")

#define LDSM4(r0, r1, r2, r3, addr) \
    asm volatile("ldmatrix.sync.aligned.m8n8.x4.shared.b16 {%0,%1,%2,%3}, [%4];" \
                 : "=r"(r0), "=r"(r1), "=r"(r2), "=r"(r3) : "r"(addr))

#define MMA16816(c, a, b0, b1) \
    asm volatile("mma.sync.aligned.m16n8k16.row.col.f32.bf16.bf16.f32 " \
                 "{%0,%1,%2,%3},{%4,%5,%6,%7},{%8,%9},{%0,%1,%2,%3};" \
                 : "+f"((c)[0]), "+f"((c)[1]), "+f"((c)[2]), "+f"((c)[3]) \
                 : "r"((a)[0]), "r"((a)[1]), "r"((a)[2]), "r"((a)[3]), \
                   "r"(b0), "r"(b1))

// ---------------------------------------------------------------------------
// bf16 split helpers
// ---------------------------------------------------------------------------
__device__ __forceinline__ uint32_t pk(__nv_bfloat16 a, __nv_bfloat16 b) {
    __nv_bfloat162 t; t.x = a; t.y = b;
    return *reinterpret_cast<uint32_t*>(&t);
}
__device__ __forceinline__ void split2(float x, float y, uint32_t& h, uint32_t& l) {
    __nv_bfloat16 hx = __float2bfloat16(x), hy = __float2bfloat16(y);
    __nv_bfloat16 lx = __float2bfloat16(x - __bfloat162float(hx));
    __nv_bfloat16 ly = __float2bfloat16(y - __bfloat162float(hy));
    h = pk(hx, hy); l = pk(lx, ly);
}
__device__ __forceinline__ void split4(const float4 v, uint2& h, uint2& l) {
    split2(v.x, v.y, h.x, l.x);
    split2(v.z, v.w, h.y, l.y);
}

// ---------------------------------------------------------------------------
// Tensor-core GEMM (mma.sync bf16, 3-term fp32-split):
//   C[r][0..511] = A[r][:] @ W^T  (+bias, +aux)
// A hi/lo with row remap: row R -> (R/rpbA)*strideA + (R%rpbA)*K (elements)
// W is [512][K] bf16 hi/lo row-major. grid = (M/128, 4), 256 threads.
// Output fp32 (outF) or re-split bf16 (outHi/outLo), row remap rpbO/strideO.
// 2 stages x 40KB smem -> 2 CTAs/SM for cross-CTA latency hiding.
// ---------------------------------------------------------------------------
constexpr int ROWB    = 80;                 // padded row stride (32 bf16 + 16B pad)
constexpr int TILEB   = 128 * ROWB;         // 10240 B per operand tile
constexpr int STAGEB  = 4 * TILEB;          // Ahi,Alo,Bhi,Blo = 40960 B
constexpr int NSTAGE  = 2;
constexpr int SMEM_GEMM = NSTAGE * STAGEB;  // 81920 B

__global__ __launch_bounds__(256, 2)
void mma_gemm(const __nv_bfloat16* __restrict__ Ahi,
              const __nv_bfloat16* __restrict__ Alo,
              int K, int rpbA, long long strideA,
              const __nv_bfloat16* __restrict__ Whi,
              const __nv_bfloat16* __restrict__ Wlo,
              const float* __restrict__ bias,
              const float* __restrict__ aux, int rpbX, long long strideX,
              float* __restrict__ outF,
              __nv_bfloat16* __restrict__ outHi, __nv_bfloat16* __restrict__ outLo,
              int rpbO, long long strideO)
{
    extern __shared__ char smem[];
    const uint32_t sbase = smem_u32(smem);

    const int tid  = threadIdx.x;
    const int wid  = tid >> 5;
    const int lane = tid & 31;
    const int bm   = blockIdx.x, bn = blockIdx.y;
    const int wm   = wid >> 2;          // 0..1  (m 64-row half)
    const int wn   = wid & 3;           // 0..3  (n 32-col quarter)

    // ---- global-load indexing: thread t -> tile row t/2, 16B units (t&1)*2,+1
    const int lr = tid >> 1;            // 0..127
    const int lu = (tid & 1) * 2;       // 0 or 2
    const int aRow = bm * 128 + lr;
    const char* aHiP = (const char*)(Ahi + (long long)(aRow / rpbA) * strideA +
                                           (long long)(aRow % rpbA) * K);
    const char* aLoP = (const char*)(Alo + (long long)(aRow / rpbA) * strideA +
                                           (long long)(aRow % rpbA) * K);
    const char* bHiP = (const char*)(Whi + (long long)(bn * 128 + lr) * K);
    const char* bLoP = (const char*)(Wlo + (long long)(bn * 128 + lr) * K);
    const uint32_t dRow = sbase + (uint32_t)lr * ROWB + (uint32_t)lu * 16;

    auto stage_load = [&](int c, int stg) {
        const uint32_t sd = dRow + (uint32_t)stg * STAGEB;
        const long long go = (long long)c * 64 + lu * 16;
        CP_ASYNC16(sd + 0 * TILEB +  0, aHiP + go);
        CP_ASYNC16(sd + 0 * TILEB + 16, aHiP + go + 16);
        CP_ASYNC16(sd + 1 * TILEB +  0, aLoP + go);
        CP_ASYNC16(sd + 1 * TILEB + 16, aLoP + go + 16);
        CP_ASYNC16(sd + 2 * TILEB +  0, bHiP + go);
        CP_ASYNC16(sd + 2 * TILEB + 16, bHiP + go + 16);
        CP_ASYNC16(sd + 3 * TILEB +  0, bLoP + go);
        CP_ASYNC16(sd + 3 * TILEB + 16, bLoP + go + 16);
    };

    // ---- ldmatrix address components (per warp/lane) ----
    const uint32_t aOffBase = (uint32_t)(wm * 64 + (lane & 15)) * ROWB +
                              (uint32_t)(lane >> 4) * 16;
    const int brow0   = wn * 32 + (lane & 7) + ((lane >> 4) << 3);
    const uint32_t bColOff = (uint32_t)((lane >> 3) & 1) * 16;

    float acc[4][4][4];
#pragma unroll
    for (int i = 0; i < 4; i++)
#pragma unroll
        for (int j = 0; j < 4; j++)
#pragma unroll
            for (int r = 0; r < 4; r++) acc[i][j][r] = 0.f;

    const int nk = K / 32;

    // prologue: stage 0
    stage_load(0, 0);
    CP_COMMIT();

    for (int c = 0; c < nk; c++) {
        CP_WAIT(0);
        __syncthreads();
        if (c + 1 < nk) stage_load(c + 1, (c + 1) & 1);
        CP_COMMIT();

        const uint32_t sb = sbase + (uint32_t)(c & 1) * STAGEB;
#pragma unroll
        for (int s = 0; s < 2; s++) {               // two k16 steps per chunk
            // B fragments for this k-step (held across the i loop)
            uint32_t bH[4][2], bL[4][2];
#pragma unroll
            for (int jp = 0; jp < 2; jp++) {
                const uint32_t ba = sb + 2 * TILEB +
                                    (uint32_t)(brow0 + jp * 16) * ROWB +
                                    bColOff + s * 32;
                LDSM4(bH[2 * jp][0], bH[2 * jp][1], bH[2 * jp + 1][0], bH[2 * jp + 1][1], ba);
                LDSM4(bL[2 * jp][0], bL[2 * jp][1], bL[2 * jp + 1][0], bL[2 * jp + 1][1], ba + TILEB);
            }
            // A fragments loaded just-in-time per m-subtile (short live range)
#pragma unroll
            for (int i = 0; i < 4; i++) {
                uint32_t aH[4], aL[4];
                const uint32_t aa = sb + aOffBase + (uint32_t)i * (16 * ROWB) + s * 32;
                LDSM4(aH[0], aH[1], aH[2], aH[3], aa);
                LDSM4(aL[0], aL[1], aL[2], aL[3], aa + TILEB);
#pragma unroll
                for (int j = 0; j < 4; j++) {
                    MMA16816(acc[i][j], aH, bH[j][0], bH[j][1]);
                    MMA16816(acc[i][j], aH, bL[j][0], bL[j][1]);
                    MMA16816(acc[i][j], aL, bH[j][0], bH[j][1]);
                }
            }
        }
        __syncthreads();
    }

    // ---- epilogue ----
    const int l4 = lane >> 2;
    const int l2 = (lane & 3) * 2;
#pragma unroll
    for (int i = 0; i < 4; i++) {
#pragma unroll
        for (int h = 0; h < 2; h++) {
            const int R = bm * 128 + wm * 64 + i * 16 + l4 + h * 8;
            const long long oBase = (long long)(R / rpbO) * strideO +
                                    (long long)(R % rpbO) * 512;
            long long xBase = 0;
            if (aux) xBase = (long long)(R / rpbX) * strideX +
                             (long long)(R % rpbX) * 512;
#pragma unroll
            for (int j = 0; j < 4; j++) {
                const int cb = bn * 128 + wn * 32 + j * 8 + l2;
                float vx = acc[i][j][h * 2 + 0];
                float vy = acc[i][j][h * 2 + 1];
                const float2 bb = *(const float2*)(bias + cb);
                vx += bb.x; vy += bb.y;
                if (aux) {
                    const float2 ax = *(const float2*)(aux + xBase + cb);
                    vx += ax.x; vy += ax.y;
                }
                if (outF) {
                    float2 o; o.x = vx; o.y = vy;
                    *(float2*)(outF + oBase + cb) = o;
                } else {
                    uint32_t hh, ll;
                    split2(vx, vy, hh, ll);
                    *(uint32_t*)(outHi + oBase + cb) = hh;
                    *(uint32_t*)(outLo + oBase + cb) = ll;
                }
            }
        }
    }
}

// ---------------------------------------------------------------------------
// Elementwise / split / reduction kernels
// ---------------------------------------------------------------------------
__global__ void split_kernel(const float4* __restrict__ src,
                             uint2* __restrict__ hi, uint2* __restrict__ lo,
                             long long n4)
{
    long long i = (long long)blockIdx.x * blockDim.x + threadIdx.x;
    if (i >= n4) return;
    uint2 h, l;
    split4(src[i], h, l);
    hi[i] = h; lo[i] = l;
}

__global__ void split_verts_kernel(const float4* __restrict__ src,
                                   uint2* __restrict__ xhi, uint2* __restrict__ xlo)
{
    long long idx = (long long)blockIdx.x * blockDim.x + threadIdx.x;
    const long long total = (long long)M_K * (D / 4);
    if (idx >= total) return;
    const int c = (int)(idx & 127);
    const long long r = idx >> 7;
    const int b = (int)(r / NV), n = (int)(r % NV);
    const long long dst = ((long long)b * NT + n) * 128 + c;
    uint2 h, l;
    split4(src[idx], h, l);
    xhi[dst] = h; xlo[dst] = l;
}

__global__ void l2norm_kernel(float* __restrict__ Q, int M,
                              const float* __restrict__ wg,
                              float* __restrict__ logit)
{
    const int gw   = (int)(((long long)blockIdx.x * blockDim.x + threadIdx.x) >> 5);
    const int lane = threadIdx.x & 31;
    if (gw >= M) return;
    float4* row = (float4*)(Q + (long long)gw * D);
    float4 v[4];
    float ss = 0.f, dg = 0.f;
#pragma unroll
    for (int i = 0; i < 4; i++) {
        v[i] = row[lane + 32 * i];
        ss += v[i].x * v[i].x + v[i].y * v[i].y + v[i].z * v[i].z + v[i].w * v[i].w;
    }
    if (wg) {
#pragma unroll
        for (int i = 0; i < 4; i++) {
            float4 w = ((const float4*)wg)[lane + 32 * i];
            dg += v[i].x * w.x + v[i].y * w.y + v[i].z * w.z + v[i].w * w.w;
        }
    }
#pragma unroll
    for (int o = 16; o > 0; o >>= 1) {
        ss += __shfl_xor_sync(0xffffffffu, ss, o);
        dg += __shfl_xor_sync(0xffffffffu, dg, o);
    }
    const float inv = 1.f / fmaxf(sqrtf(ss), 1e-12f);
#pragma unroll
    for (int i = 0; i < 4; i++) {
        v[i].x *= inv; v[i].y *= inv; v[i].z *= inv; v[i].w *= inv;
        row[lane + 32 * i] = v[i];
    }
    if (wg && lane == 0) logit[gw] = dg * inv * ATTN_SCALE;
}

__global__ void softmax_stats_kernel(const float* __restrict__ logit,
                                     float* __restrict__ stats)
{
    const int b = blockIdx.x;
    const int tid = threadIdx.x;
    __shared__ float red[256];
    float mx = -1e30f;
    for (int n = tid; n < NT; n += 256) mx = fmaxf(mx, logit[b * NT + n]);
    red[tid] = mx; __syncthreads();
    for (int s = 128; s > 0; s >>= 1) {
        if (tid < s) red[tid] = fmaxf(red[tid], red[tid + s]);
        __syncthreads();
    }
    const float m = red[0]; __syncthreads();
    float se = 0.f;
    for (int n = tid; n < NT; n += 256) se += expf(logit[b * NT + n] - m);
    red[tid] = se; __syncthreads();
    for (int s = 128; s > 0; s >>= 1) {
        if (tid < s) red[tid] += red[tid + s];
        __syncthreads();
    }
    if (tid == 0) { stats[2 * b] = m; stats[2 * b + 1] = red[0]; }
}

__global__ void compute_g_kernel(const float* __restrict__ q,
                                 const float* __restrict__ logit,
                                 const float* __restrict__ stats,
                                 float* __restrict__ g)
{
    const int b = blockIdx.x;
    const int d = blockIdx.y * 128 + threadIdx.x;
    const float m = stats[2 * b];
    const float inv_s = 1.f / stats[2 * b + 1];
    __shared__ float w[128];
    float acc = 0.f;
    const float* qb = q + (long long)b * NT * D;
    for (int n0 = 0; n0 < NT; n0 += 128) {
        const int n = n0 + threadIdx.x;
        w[threadIdx.x] = (n < NT) ? expf(logit[b * NT + n] - m) * inv_s : 0.f;
        __syncthreads();
        const int lim = min(128, NT - n0);
        for (int j = 0; j < lim; j++)
            acc += w[j] * qb[(long long)(n0 + j) * D + d];
        __syncthreads();
    }
    g[b * D + d] = acc;
}

__global__ void scale_split_k_kernel(const float4* __restrict__ k,
                                     const float4* __restrict__ g,
                                     uint2* __restrict__ hi, uint2* __restrict__ lo)
{
    long long idx = (long long)blockIdx.x * blockDim.x + threadIdx.x;
    const long long total = (long long)M_K * (D / 4);
    if (idx >= total) return;
    const int c = (int)(idx & 127);
    const int b = (int)((idx >> 7) / NV);
    float4 kv = k[idx];
    const float4 gv = g[b * 128 + c];
    kv.x *= gv.x; kv.y *= gv.y; kv.z *= gv.z; kv.w *= gv.w;
    uint2 h, l;
    split4(kv, h, l);
    hi[idx] = h; lo[idx] = l;
}

// ---------------------------------------------------------------------------
// launch
// ---------------------------------------------------------------------------
extern "C" void kernel_launch(void* const* d_in, const int* in_sizes, int n_in,
                              void* d_out, int out_size)
{
    (void)in_sizes; (void)n_in; (void)out_size;

    const float* verts_f = (const float*)d_in[0];
    const float* img_f   = (const float*)d_in[1];
    const float* fc_w    = (const float*)d_in[2];
    const float* fc_b    = (const float*)d_in[3];
    const float* q_w     = (const float*)d_in[4];
    const float* q_b     = (const float*)d_in[5];
    const float* k_w     = (const float*)d_in[6];
    const float* k_b     = (const float*)d_in[7];
    const float* w_g     = (const float*)d_in[8];
    const float* proj_w  = (const float*)d_in[9];
    const float* proj_b  = (const float*)d_in[10];
    const float* final_w = (const float*)d_in[11];
    const float* final_b = (const float*)d_in[12];
    float* out = (float*)d_out;

    __nv_bfloat16 *xhi, *xlo, *ihi, *ilo, *gkhi, *gklo, *thi, *tlo, *whi, *wlo;
    float *q, *k, *logit, *stats, *gq;
    cudaGetSymbolAddress((void**)&xhi,  g_xhi);
    cudaGetSymbolAddress((void**)&xlo,  g_xlo);
    cudaGetSymbolAddress((void**)&ihi,  g_ihi);
    cudaGetSymbolAddress((void**)&ilo,  g_ilo);
    cudaGetSymbolAddress((void**)&gkhi, g_gkhi);
    cudaGetSymbolAddress((void**)&gklo, g_gklo);
    cudaGetSymbolAddress((void**)&thi,  g_thi);
    cudaGetSymbolAddress((void**)&tlo,  g_tlo);
    cudaGetSymbolAddress((void**)&whi,  g_whi);
    cudaGetSymbolAddress((void**)&wlo,  g_wlo);
    cudaGetSymbolAddress((void**)&q,     g_q);
    cudaGetSymbolAddress((void**)&k,     g_k);
    cudaGetSymbolAddress((void**)&logit, g_logit);
    cudaGetSymbolAddress((void**)&stats, g_stats);
    cudaGetSymbolAddress((void**)&gq,    g_gq);

    cudaFuncSetAttribute(mma_gemm, cudaFuncAttributeMaxDynamicSharedMemorySize,
                         SMEM_GEMM);

    const long long sNT = (long long)NT * D;
    const long long ewT = (long long)M_K * (D / 4);
    const int ewB = (int)((ewT + 255) / 256);

    // --- input splits ---
    auto splt = [&](const float* src, __nv_bfloat16* h, __nv_bfloat16* l, long long n) {
        long long n4 = n / 4;
        split_kernel<<<(int)((n4 + 255) / 256), 256>>>(
            (const float4*)src, (uint2*)h, (uint2*)l, n4);
    };
    splt(fc_w,    whi + OFF_FC, wlo + OFF_FC, (long long)D * IMGD);
    splt(q_w,     whi + OFF_QW, wlo + OFF_QW, (long long)D * D);
    splt(k_w,     whi + OFF_KW, wlo + OFF_KW, (long long)D * D);
    splt(proj_w,  whi + OFF_PW, wlo + OFF_PW, (long long)D * D);
    splt(img_f,   ihi, ilo, (long long)M_IMG * IMGD);
    splt(final_w, whi + OFF_FW, wlo + OFF_FW, (long long)D * D);
    split_verts_kernel<<<ewB, 256>>>((const float4*)verts_f,
                                     (uint2*)xhi, (uint2*)xlo);

    // --- 1) x[:, NV:] = img_f @ fc_w^T + fc_b  (split output into x hi/lo) ---
    mma_gemm<<<dim3(M_IMG / 128, 4), 256, SMEM_GEMM>>>(
        ihi, ilo, IMGD, M_IMG, 0LL,
        whi + OFF_FC, wlo + OFF_FC, fc_b,
        nullptr, 1, 0LL,
        nullptr, xhi + (long long)NV * D, xlo + (long long)NV * D,
        NI, sNT);

    // --- 2) q = x @ q_w^T + q_b (all tokens, fp32 out) ---
    mma_gemm<<<dim3(M_Q / 128, 4), 256, SMEM_GEMM>>>(
        xhi, xlo, D, M_Q, 0LL,
        whi + OFF_QW, wlo + OFF_QW, q_b,
        nullptr, 1, 0LL,
        q, nullptr, nullptr, M_Q, 0LL);
    l2norm_kernel<<<(M_Q * 32 + 255) / 256, 256>>>(q, M_Q, w_g, logit);

    // --- 3) k = x_vert @ k_w^T + k_b (vertex tokens, fp32 out) ---
    mma_gemm<<<dim3(M_K / 128, 4), 256, SMEM_GEMM>>>(
        xhi, xlo, D, NV, sNT,
        whi + OFF_KW, wlo + OFF_KW, k_b,
        nullptr, 1, 0LL,
        k, nullptr, nullptr, M_K, 0LL);
    l2norm_kernel<<<(M_K * 32 + 255) / 256, 256>>>(k, M_K, nullptr, nullptr);

    // --- 4) softmax + global query ---
    softmax_stats_kernel<<<B, 256>>>(logit, stats);
    compute_g_kernel<<<dim3(B, 4), 128>>>(q, logit, stats, gq);

    // --- 5) gk = g * k, split ---
    scale_split_k_kernel<<<ewB, 256>>>((const float4*)k, (const float4*)gq,
                                       (uint2*)gkhi, (uint2*)gklo);

    // --- 6) t = gk @ proj_w^T + proj_b + q_vert (split output) ---
    mma_gemm<<<dim3(M_K / 128, 4), 256, SMEM_GEMM>>>(
        gkhi, gklo, D, M_K, 0LL,
        whi + OFF_PW, wlo + OFF_PW, proj_b,
        q, NV, sNT,
        nullptr, thi, tlo, M_K, 0LL);

    // --- 7) out = t @ final_w^T + final_b + verts_f (fp32 out) ---
    mma_gemm<<<dim3(M_K / 128, 4), 256, SMEM_GEMM>>>(
        thi, tlo, D, M_K, 0LL,
        whi + OFF_FW, wlo + OFF_FW, final_b,
        verts_f, M_K, 0LL,
        out, nullptr, nullptr, M_K, 0LL);
}